// round 1
// baseline (speedup 1.0000x reference)
#include <cuda_runtime.h>
#include <cuda_bf16.h>

#define BROWS 16384
#define HDIM  2048
#define NSEG  8
#define SEG   (HDIM / NSEG)   // 256
#define HC    128             // h chunk staged in smem
#define RT    128             // rows per block (= threads per block)
#define SMEM_BYTES ((HC * 128 + SEG * 16) * 4)  // xs + ws = 81920 B

// 13 useful columns padded to 16: [0..3]=Wg, [4..7]=Wp, [8..12]=Wa, rest 0
__device__ float g_wpack[HDIM * 16];
// partial sums: [seg][row][16]
__device__ float g_part[NSEG * BROWS * 16];

__device__ __forceinline__ unsigned long long pack2(float a, float b) {
    unsigned long long r;
    asm("mov.b64 %0, {%1, %2};" : "=l"(r) : "f"(a), "f"(b));
    return r;
}
__device__ __forceinline__ void unpack2(unsigned long long v, float& a, float& b) {
    asm("mov.b64 {%0, %1}, %2;" : "=f"(a), "=f"(b) : "l"(v));
}
__device__ __forceinline__ unsigned long long ffma2(unsigned long long a,
                                                    unsigned long long b,
                                                    unsigned long long c) {
    unsigned long long d;
    asm("fma.rn.f32x2 %0, %1, %2, %3;" : "=l"(d) : "l"(a), "l"(b), "l"(c));
    return d;
}

// ---------------------------------------------------------------------------
// Kernel 1: pack weights into [H][16] rows
// ---------------------------------------------------------------------------
__global__ void pack_k(const float* __restrict__ Wg,
                       const float* __restrict__ Wp,
                       const float* __restrict__ Wa) {
    int h = blockIdx.x * blockDim.x + threadIdx.x;
    if (h >= HDIM) return;
    float* d = g_wpack + h * 16;
#pragma unroll
    for (int c = 0; c < 4; c++) d[c]     = Wg[h * 4 + c];
#pragma unroll
    for (int c = 0; c < 4; c++) d[4 + c] = Wp[h * 4 + c];
#pragma unroll
    for (int c = 0; c < 5; c++) d[8 + c] = Wa[h * 5 + c];
    d[13] = 0.f; d[14] = 0.f; d[15] = 0.f;
}

// ---------------------------------------------------------------------------
// Kernel 2: main GEMM partials. grid = (BROWS/RT, NSEG), block = RT threads.
// Each thread owns one row, accumulates 13 (padded to 14) dot products over
// its h-segment using packed f32x2 FMA (column pairs).
// ---------------------------------------------------------------------------
__global__ void main_k(const float* __restrict__ x) {
    extern __shared__ float smem[];
    float* xs = smem;                 // [HC][128] transposed + XOR swizzled
    float* ws = smem + HC * 128;      // [SEG][16]

    const int tid  = threadIdx.x;
    const int row0 = blockIdx.x * RT;
    const int h0   = blockIdx.y * SEG;

    // stage weight segment: SEG*16 floats = 1024 float4
    {
        const float4* src = (const float4*)(g_wpack + (size_t)h0 * 16);
        float4* dst = (float4*)ws;
#pragma unroll
        for (int i = 0; i < (SEG * 16 / 4) / RT; i++)
            dst[tid + i * RT] = src[tid + i * RT];
    }

    unsigned long long acc[7];
#pragma unroll
    for (int i = 0; i < 7; i++) acc[i] = 0ull;

    for (int hc = 0; hc < SEG; hc += HC) {
        __syncthreads();
        // stage x tile [RT rows][HC cols] -> transposed swizzled smem
#pragma unroll
        for (int i = 0; i < (RT * HC / 4) / RT; i++) {   // 32 iters
            int idx = tid + (i << 7);       // over RT*HC/4 float4s
            int r   = idx >> 5;             // HC/4 = 32 float4 per row
            int c4  = idx & 31;
            float4 v = __ldcs((const float4*)(x + (size_t)(row0 + r) * HDIM
                                              + h0 + hc + (c4 << 2)));
            int h4 = c4 << 2;
            int rs = r ^ c4;                // swizzle: (h>>2)&31 == c4
            xs[(h4 + 0) * 128 + rs] = v.x;
            xs[(h4 + 1) * 128 + rs] = v.y;
            xs[(h4 + 2) * 128 + rs] = v.z;
            xs[(h4 + 3) * 128 + rs] = v.w;
        }
        __syncthreads();

#pragma unroll 4
        for (int h4 = 0; h4 < HC; h4 += 4) {
            const int rs = tid ^ ((h4 >> 2) & 31);
            const float* xp = xs + h4 * 128 + rs;
#pragma unroll
            for (int j = 0; j < 4; j++) {
                float xv = xp[j * 128];
                unsigned long long x2 = pack2(xv, xv);
                const float* wr = ws + (size_t)(hc + h4 + j) * 16;
                ulonglong2 wA = *(const ulonglong2*)(wr);       // cols 0..3
                ulonglong2 wB = *(const ulonglong2*)(wr + 4);   // cols 4..7
                ulonglong2 wC = *(const ulonglong2*)(wr + 8);   // cols 8..11
                unsigned long long wD = *(const unsigned long long*)(wr + 12); // 12,13
                acc[0] = ffma2(x2, wA.x, acc[0]);
                acc[1] = ffma2(x2, wA.y, acc[1]);
                acc[2] = ffma2(x2, wB.x, acc[2]);
                acc[3] = ffma2(x2, wB.y, acc[3]);
                acc[4] = ffma2(x2, wC.x, acc[4]);
                acc[5] = ffma2(x2, wC.y, acc[5]);
                acc[6] = ffma2(x2, wD,   acc[6]);
            }
        }
    }

    // write partials: 14 values (col 13 is zero) padded to 16
    float v[16];
#pragma unroll
    for (int i = 0; i < 7; i++) unpack2(acc[i], v[2 * i], v[2 * i + 1]);
    v[14] = 0.f; v[15] = 0.f;
    float4* dst = (float4*)(g_part + ((size_t)blockIdx.y * BROWS + row0 + tid) * 16);
#pragma unroll
    for (int i = 0; i < 4; i++)
        dst[i] = make_float4(v[4 * i], v[4 * i + 1], v[4 * i + 2], v[4 * i + 3]);
}

// ---------------------------------------------------------------------------
// Kernel 3: reduce partials + softmaxes + safety marginalization
// ---------------------------------------------------------------------------
__global__ void epi_k(const float* __restrict__ bg,
                      const float* __restrict__ bp,
                      const float* __restrict__ ba,
                      float* __restrict__ out) {
    const int r = blockIdx.x * blockDim.x + threadIdx.x;
    if (r >= BROWS) return;

    float v[16];
    {
        const float4* p0 = (const float4*)(g_part + (size_t)r * 16);
        float4 a0 = p0[0], a1 = p0[1], a2 = p0[2], a3 = p0[3];
#pragma unroll
        for (int s = 1; s < NSEG; s++) {
            const float4* p = (const float4*)(g_part + ((size_t)s * BROWS + r) * 16);
            float4 b0 = p[0], b1 = p[1], b2 = p[2], b3 = p[3];
            a0.x += b0.x; a0.y += b0.y; a0.z += b0.z; a0.w += b0.w;
            a1.x += b1.x; a1.y += b1.y; a1.z += b1.z; a1.w += b1.w;
            a2.x += b2.x; a2.y += b2.y; a2.z += b2.z; a2.w += b2.w;
            a3.x += b3.x; a3.y += b3.y; a3.z += b3.z; a3.w += b3.w;
        }
        *(float4*)(v + 0)  = a0; *(float4*)(v + 4)  = a1;
        *(float4*)(v + 8)  = a2; *(float4*)(v + 12) = a3;
    }

    const float LOG2E = 1.4426950408889634f;

    // ghost softmax (cols 0..3)
    float G[4], P[4], A[5];
#pragma unroll
    for (int c = 0; c < 4; c++) G[c] = v[c] + bg[c];
#pragma unroll
    for (int c = 0; c < 4; c++) P[c] = v[4 + c] + bp[c];
#pragma unroll
    for (int c = 0; c < 5; c++) A[c] = v[8 + c] + ba[c];

    float mg = fmaxf(fmaxf(G[0], G[1]), fmaxf(G[2], G[3]));
    float sg = 0.f;
#pragma unroll
    for (int c = 0; c < 4; c++) { G[c] = exp2f((G[c] - mg) * LOG2E); sg += G[c]; }
    float ig = 1.f / sg;
#pragma unroll
    for (int c = 0; c < 4; c++) G[c] *= ig;

    float mp = fmaxf(fmaxf(P[0], P[1]), fmaxf(P[2], P[3]));
    float sp = 0.f;
#pragma unroll
    for (int c = 0; c < 4; c++) { P[c] = exp2f((P[c] - mp) * LOG2E); sp += P[c]; }
    float ip = 1.f / sp;
#pragma unroll
    for (int c = 0; c < 4; c++) P[c] *= ip;

    float ma = fmaxf(fmaxf(fmaxf(A[0], A[1]), fmaxf(A[2], A[3])), A[4]);
    float sa = 0.f;
#pragma unroll
    for (int c = 0; c < 5; c++) { A[c] = exp2f((A[c] - ma) * LOG2E); sa += A[c]; }
    float ia = 1.f / sa;
#pragma unroll
    for (int c = 0; c < 5; c++) A[c] *= ia;

    // unsafe per action
    float u0 = P[0] * G[0] + P[1] * G[1] + P[2] * G[2] + P[3] * G[3]; // stay
    float u1 = P[0] * G[1] + P[2] * G[3];                             // up
    float u2 = P[1] * G[0] + P[3] * G[2];                             // down

    float j0 = A[0] * (1.f - u0);
    float j1 = A[1] * (1.f - u1);
    float j2 = A[2] * (1.f - u2);
    float j3 = A[3];
    float j4 = A[4];
    float inv = 1.f / (j0 + j1 + j2 + j3 + j4);

    float* o = out + (size_t)r * 5;
    o[0] = j0 * inv; o[1] = j1 * inv; o[2] = j2 * inv;
    o[3] = j3 * inv; o[4] = j4 * inv;
}

// ---------------------------------------------------------------------------
extern "C" void kernel_launch(void* const* d_in, const int* in_sizes, int n_in,
                              void* d_out, int out_size) {
    const float* x  = (const float*)d_in[0];
    const float* Wg = (const float*)d_in[1];
    const float* bg = (const float*)d_in[2];
    const float* Wp = (const float*)d_in[3];
    const float* bp = (const float*)d_in[4];
    const float* Wa = (const float*)d_in[5];
    const float* ba = (const float*)d_in[6];
    float* out = (float*)d_out;

    cudaFuncSetAttribute(main_k, cudaFuncAttributeMaxDynamicSharedMemorySize,
                         SMEM_BYTES);

    pack_k<<<(HDIM + 255) / 256, 256>>>(Wg, Wp, Wa);
    main_k<<<dim3(BROWS / RT, NSEG), RT, SMEM_BYTES>>>(x);
    epi_k<<<(BROWS + 255) / 256, 256>>>(bg, bp, ba, out);
}